// round 12
// baseline (speedup 1.0000x reference)
#include <cuda_runtime.h>
#include <cuda_bf16.h>
#include <mma.h>

using namespace nvcuda;

#define B_ 2
#define L_ 2048
#define D_ 128
#define H_ 8
#define HD_ 32
#define HB_ 16
#define QSCALE 0.1767766953f

__device__ float g_Z[HB_ * L_];
__device__ float g_S[HB_ * L_];
__device__ float g_vv[HB_ * L_];
__device__ __nv_bfloat16 g_Q[HB_ * L_ * HD_];
__device__ __nv_bfloat16 g_K[HB_ * L_ * HD_];

__global__ void qk_kernel(const float* __restrict__ x, const float* __restrict__ pe,
                          const float* __restrict__ Wq, const float* __restrict__ bq,
                          const float* __restrict__ Wk, const float* __restrict__ bk) {
    __shared__ float xs[16][D_];
    int row0 = blockIdx.x * 16;
    int tg = blockIdx.x * 256 + threadIdx.x;
    if (tg < HB_ * L_) {
        g_Z[tg] = 0.f;
        g_S[tg] = 0.f;
    }
    for (int i = threadIdx.x; i < 16 * D_; i += 256) {
        int r = i >> 7;
        int d = i & (D_ - 1);
        int row = row0 + r;
        int l = row & (L_ - 1);
        xs[r][d] = x[row * D_ + d] + pe[l * D_ + d];
    }
    __syncthreads();

    int c = threadIdx.x;
    float accq[16];
    float acck[16];
#pragma unroll
    for (int r = 0; r < 16; r++) {
        accq[r] = 0.f;
        acck[r] = 0.f;
    }
#pragma unroll 4
    for (int d = 0; d < D_; d++) {
        float wq = Wq[d * 256 + c];
        float wk = Wk[d * 256 + c];
#pragma unroll
        for (int r = 0; r < 16; r++) {
            float xv = xs[r][d];
            accq[r] = fmaf(xv, wq, accq[r]);
            acck[r] = fmaf(xv, wk, acck[r]);
        }
    }
    float bqv = bq[c];
    float bkv = bk[c];
    int h = c >> 5;
    int hd = c & 31;
#pragma unroll
    for (int r = 0; r < 16; r++) {
        int row = row0 + r;
        int b = row >> 11;
        int l = row & (L_ - 1);
        size_t off = ((size_t)(h * B_ + b) * L_ + l) * HD_ + hd;
        g_Q[off] = __float2bfloat16((accq[r] + bqv) * QSCALE);
        g_K[off] = __float2bfloat16(acck[r] + bkv);
    }
}

__global__ void v_kernel(const float* __restrict__ x, const float* __restrict__ Wv) {
    int t = blockIdx.x * 256 + threadIdx.x;
    int h = t & 7;
    int row = t >> 3;
    const float* xr = x + (size_t)row * D_;
    float acc = 0.f;
#pragma unroll 8
    for (int d = 0; d < D_; d++) acc = fmaf(xr[d], Wv[d * H_ + h], acc);
    float s = 1.f / (1.f + __expf(-acc));
    int b = row >> 11;
    int l = row & (L_ - 1);
    g_vv[(h * B_ + b) * L_ + (L_ - 1 - l)] = s;
}

// Pass 1: Z row sums, __expf direct from accumulator registers.
// Layout discovered at runtime by a probe MMA (A = I, B[k][c] = k + 16c).
// grid (32, 16, 4), block 128.
__global__ __launch_bounds__(128) void z_kernel() {
    __shared__ __nv_bfloat16 Qs[64 * HD_];
    __shared__ __nv_bfloat16 Ks[64 * HD_];
    __shared__ __nv_bfloat16 Pa[4][256];
    __shared__ __nv_bfloat16 Pb[4][256];
    __shared__ float zrow[4][16];

    int hb = blockIdx.y;
    int q0 = blockIdx.x * 64;
    int kc0 = blockIdx.z * 512;
    int tid = threadIdx.x;
    int w = tid >> 5;
    int lane = tid & 31;

    int rowi[8];
    for (int i = lane; i < 256; i += 32) {
        int pr = i >> 4;
        int pk = i & 15;
        Pa[w][i] = __float2bfloat16(pr == pk ? 1.f : 0.f);
        Pb[w][i] = __float2bfloat16((float)i);
    }
    __syncwarp();
    {
        wmma::fragment<wmma::matrix_a, 16, 16, 16, __nv_bfloat16, wmma::row_major> ap;
        wmma::fragment<wmma::matrix_b, 16, 16, 16, __nv_bfloat16, wmma::col_major> bp;
        wmma::fragment<wmma::accumulator, 16, 16, 16, float> cp;
        wmma::load_matrix_sync(ap, &Pa[w][0], 16);
        wmma::load_matrix_sync(bp, &Pb[w][0], 16);
        wmma::fill_fragment(cp, 0.f);
        wmma::mma_sync(cp, ap, bp, cp);
#pragma unroll
        for (int i = 0; i < 8; i++) {
            int v = (int)(cp.x[i] + 0.5f);
            rowi[i] = v & 15;
        }
    }

    const uint4* qsrc = (const uint4*)(g_Q + ((size_t)hb * L_ + q0) * HD_);
    uint4* qdst = (uint4*)Qs;
    for (int i = tid; i < 256; i += 128) qdst[i] = qsrc[i];
    __syncthreads();

    wmma::fragment<wmma::matrix_a, 16, 16, 16, __nv_bfloat16, wmma::row_major> a0, a1;
    wmma::load_matrix_sync(a0, Qs + w * 16 * HD_, HD_);
    wmma::load_matrix_sync(a1, Qs + w * 16 * HD_ + 16, HD_);

    float zpart[8];
#pragma unroll
    for (int i = 0; i < 8; i++) zpart[i] = 0.f;

    for (int kt = 0; kt < 8; kt++) {
        __syncthreads();
        const uint4* ksrc = (const uint4*)(g_K + ((size_t)hb * L_ + kc0 + kt * 64) * HD_);
        uint4* kdst = (uint4*)Ks;
        for (int i = tid; i < 256; i += 128) kdst[i] = ksrc[i];
        __syncthreads();

#pragma unroll
        for (int n = 0; n < 4; n++) {
            wmma::fragment<wmma::matrix_b, 16, 16, 16, __nv_bfloat16, wmma::col_major> b0, b1;
            wmma::load_matrix_sync(b0, Ks + n * 16 * HD_, HD_);
            wmma::load_matrix_sync(b1, Ks + n * 16 * HD_ + 16, HD_);
            wmma::fragment<wmma::accumulator, 16, 16, 16, float> cf;
            wmma::fill_fragment(cf, 0.f);
            wmma::mma_sync(cf, a0, b0, cf);
            wmma::mma_sync(cf, a1, b1, cf);
#pragma unroll
            for (int i = 0; i < 8; i++) zpart[i] += __expf(cf.x[i]);
        }
    }

    if (lane < 16) zrow[w][lane] = 0.f;
    __syncwarp();
#pragma unroll
    for (int i = 0; i < 8; i++) atomicAdd(&zrow[w][rowi[i]], zpart[i]);
    __syncwarp();
    if (lane < 16) atomicAdd(&g_Z[hb * L_ + q0 + w * 16 + lane], zrow[w][lane]);
}

// Pass 2: diagonal sums. p computed in registers (probed layout), scattered
// to a skewed per-warp stash (column == diagonal id). Skew borders pre-zeroed
// so the gather is an unconditional unrolled 16-row sum; results go straight
// to g_S via atomics. grid (32, 16, 4), block 128. smem ~31 KB.
__global__ __launch_bounds__(128) void s_kernel() {
    __shared__ __nv_bfloat16 Qs[64 * HD_];
    __shared__ __nv_bfloat16 Ks[64 * HD_];
    __shared__ float invZs[64];
    __shared__ float vvs[512];
    __shared__ float stash[4][16 * 80];

    int hb = blockIdx.y;
    int q0 = blockIdx.x * 64;
    int kc0 = blockIdx.z * 512;
    if (kc0 + 511 < q0) return;

    int tid = threadIdx.x;
    int w = tid >> 5;
    int lane = tid & 31;
    float* stw = &stash[w][0];

    // probe buffers overlay the stash (consumed before stash is used)
    int rowi[8];
    int coli[8];
    {
        __nv_bfloat16* Paw = (__nv_bfloat16*)stw;
        __nv_bfloat16* Pbw = Paw + 256;
        for (int i = lane; i < 256; i += 32) {
            int pr = i >> 4;
            int pk = i & 15;
            Paw[i] = __float2bfloat16(pr == pk ? 1.f : 0.f);
            Pbw[i] = __float2bfloat16((float)i);
        }
        __syncwarp();
        wmma::fragment<wmma::matrix_a, 16, 16, 16, __nv_bfloat16, wmma::row_major> ap;
        wmma::fragment<wmma::matrix_b, 16, 16, 16, __nv_bfloat16, wmma::col_major> bp;
        wmma::fragment<wmma::accumulator, 16, 16, 16, float> cp;
        wmma::load_matrix_sync(ap, Paw, 16);
        wmma::load_matrix_sync(bp, Pbw, 16);
        wmma::fill_fragment(cp, 0.f);
        wmma::mma_sync(cp, ap, bp, cp);
#pragma unroll
        for (int i = 0; i < 8; i++) {
            int v = (int)(cp.x[i] + 0.5f);
            rowi[i] = v & 15;
            coli[i] = v >> 4;
        }
        __syncwarp();
    }

    // pre-zero the never-written skew borders (valid scatter region is
    // index r*80 + t with t in [15-r, 79-r))
#pragma unroll
    for (int rr = 0; rr < 16; rr++) {
        if (lane < 15 - rr) stw[rr * 80 + lane] = 0.f;
        if (lane < rr) stw[rr * 80 + 79 - rr + lane] = 0.f;
    }

    const uint4* qsrc = (const uint4*)(g_Q + ((size_t)hb * L_ + q0) * HD_);
    uint4* qdst = (uint4*)Qs;
    for (int i = tid; i < 256; i += 128) qdst[i] = qsrc[i];
    if (tid < 64) invZs[tid] = 1.f / g_Z[hb * L_ + q0 + tid];
    for (int i = tid; i < 512; i += 128) vvs[i] = g_vv[hb * L_ + kc0 + i];
    __syncthreads();

    wmma::fragment<wmma::matrix_a, 16, 16, 16, __nv_bfloat16, wmma::row_major> a0, a1;
    wmma::load_matrix_sync(a0, Qs + w * 16 * HD_, HD_);
    wmma::load_matrix_sync(a1, Qs + w * 16 * HD_ + 16, HD_);

    int q0w = q0 + w * 16;
    float iz[8];
    int soff[8];
#pragma unroll
    for (int i = 0; i < 8; i++) {
        iz[i] = invZs[w * 16 + rowi[i]];
        soff[i] = rowi[i] * 79 + 15;
    }

    for (int kt = 0; kt < 8; kt++) {
        int k0 = kc0 + kt * 64;
        if (k0 + 63 < q0) continue;
        __syncthreads();
        const uint4* ksrc = (const uint4*)(g_K + ((size_t)hb * L_ + k0) * HD_);
        uint4* kdst = (uint4*)Ks;
        for (int i = tid; i < 256; i += 128) kdst[i] = ksrc[i];
        __syncthreads();

#pragma unroll
        for (int n = 0; n < 4; n++) {
            wmma::fragment<wmma::matrix_b, 16, 16, 16, __nv_bfloat16, wmma::col_major> b0, b1;
            wmma::load_matrix_sync(b0, Ks + n * 16 * HD_, HD_);
            wmma::load_matrix_sync(b1, Ks + n * 16 * HD_ + 16, HD_);
            wmma::fragment<wmma::accumulator, 16, 16, 16, float> cf;
            wmma::fill_fragment(cf, 0.f);
            wmma::mma_sync(cf, a0, b0, cf);
            wmma::mma_sync(cf, a1, b1, cf);
#pragma unroll
            for (int i = 0; i < 8; i++) {
                int c = n * 16 + coli[i];
                float p = __expf(cf.x[i]) * iz[i] * vvs[kt * 64 + c];
                stw[soff[i] + c] = p;
            }
        }
        __syncwarp();

        int mbase = k0 - q0w;
        for (int t = lane; t < 79; t += 32) {
            float sum = 0.f;
#pragma unroll
            for (int rr = 0; rr < 16; rr++) {
                sum += stw[rr * 80 + t];
            }
            int m = mbase + t - 15;
            if (m >= 0) atomicAdd(&g_S[hb * L_ + m], sum);
        }
        __syncwarp();
    }
}

__global__ void out_kernel(float* __restrict__ out) {
    int t = blockIdx.x * 256 + threadIdx.x;
    int h = t & 7;
    int m = (t >> 3) & (L_ - 1);
    int b = t >> 14;
    const float* S = g_S + (h * B_ + b) * L_;
    float num = S[m];
    float cnt = 3.f;
    if (m > 0) num += S[m - 1]; else cnt = 2.f;
    if (m < L_ - 1) num += S[m + 1]; else cnt = 2.f;
    out[t] = num / cnt;
}

extern "C" void kernel_launch(void* const* d_in, const int* in_sizes, int n_in,
                              void* d_out, int out_size) {
    const float* x = (const float*)d_in[0];
    const float* pe = (const float*)d_in[1];
    const float* Wq = (const float*)d_in[2];
    const float* bq = (const float*)d_in[3];
    const float* Wk = (const float*)d_in[4];
    const float* bk = (const float*)d_in[5];
    const float* Wv = (const float*)d_in[6];
    float* out = (float*)d_out;

    qk_kernel<<<256, 256>>>(x, pe, Wq, bq, Wk, bk);
    v_kernel<<<128, 256>>>(x, Wv);
    z_kernel<<<dim3(32, 16, 4), 128>>>();
    s_kernel<<<dim3(32, 16, 4), 128>>>();
    out_kernel<<<128, 256>>>(out);
}

// round 14
// speedup vs baseline: 1.5922x; 1.5922x over previous
#include <cuda_runtime.h>
#include <cuda_bf16.h>
#include <mma.h>

using namespace nvcuda;

#define B_ 2
#define L_ 2048
#define D_ 128
#define H_ 8
#define HD_ 32
#define HB_ 16
#define QSCALE 0.2550348f

__device__ float g_Z[HB_ * L_];
__device__ float g_S[HB_ * L_];
__device__ float g_vv[HB_ * L_];
__device__ __nv_bfloat16 g_Q[HB_ * L_ * HD_];
__device__ __nv_bfloat16 g_K[HB_ * L_ * HD_];

__global__ void qk_kernel(const float* __restrict__ x, const float* __restrict__ pe,
                          const float* __restrict__ Wq, const float* __restrict__ bq,
                          const float* __restrict__ Wk, const float* __restrict__ bk) {
    __shared__ float xs[16][D_];
    int row0 = blockIdx.x * 16;
    int tg = blockIdx.x * 256 + threadIdx.x;
    if (tg < HB_ * L_) {
        g_Z[tg] = 0.f;
        g_S[tg] = 0.f;
    }
    for (int i = threadIdx.x; i < 16 * D_; i += 256) {
        int r = i >> 7;
        int d = i & (D_ - 1);
        int row = row0 + r;
        int l = row & (L_ - 1);
        xs[r][d] = x[row * D_ + d] + pe[l * D_ + d];
    }
    __syncthreads();

    int c = threadIdx.x;
    float accq[16];
    float acck[16];
#pragma unroll
    for (int r = 0; r < 16; r++) {
        accq[r] = 0.f;
        acck[r] = 0.f;
    }
#pragma unroll 4
    for (int d = 0; d < D_; d++) {
        float wq = Wq[d * 256 + c];
        float wk = Wk[d * 256 + c];
#pragma unroll
        for (int r = 0; r < 16; r++) {
            float xv = xs[r][d];
            accq[r] = fmaf(xv, wq, accq[r]);
            acck[r] = fmaf(xv, wk, acck[r]);
        }
    }
    float bqv = bq[c];
    float bkv = bk[c];
    int h = c >> 5;
    int hd = c & 31;
#pragma unroll
    for (int r = 0; r < 16; r++) {
        int row = row0 + r;
        int b = row >> 11;
        int l = row & (L_ - 1);
        size_t off = ((size_t)(h * B_ + b) * L_ + l) * HD_ + hd;
        g_Q[off] = __float2bfloat16((accq[r] + bqv) * QSCALE);
        g_K[off] = __float2bfloat16(acck[r] + bkv);
    }
}

__global__ void v_kernel(const float* __restrict__ x, const float* __restrict__ Wv) {
    int t = blockIdx.x * 256 + threadIdx.x;
    int h = t & 7;
    int row = t >> 3;
    const float* xr = x + (size_t)row * D_;
    float acc = 0.f;
#pragma unroll 8
    for (int d = 0; d < D_; d++) acc = fmaf(xr[d], Wv[d * H_ + h], acc);
    float s = 1.f / (1.f + __expf(-acc));
    int b = row >> 11;
    int l = row & (L_ - 1);
    g_vv[(h * B_ + b) * L_ + (L_ - 1 - l)] = s;
}

// Pass 1: Z row sums, exp2 direct from accumulator registers.
// Layout discovered at runtime by a probe MMA (A = I, B[k][c] = k + 16c).
// grid (32, 16, 4), block 128.
__global__ __launch_bounds__(128) void z_kernel() {
    __shared__ __nv_bfloat16 Qs[64 * HD_];
    __shared__ __nv_bfloat16 Ks[64 * HD_];
    __shared__ __nv_bfloat16 Pa[4][256];
    __shared__ __nv_bfloat16 Pb[4][256];
    __shared__ float zrow[4][16];

    int hb = blockIdx.y;
    int q0 = blockIdx.x * 64;
    int kc0 = blockIdx.z * 512;
    int tid = threadIdx.x;
    int w = tid >> 5;
    int lane = tid & 31;

    int rowi[8];
    for (int i = lane; i < 256; i += 32) {
        int pr = i >> 4;
        int pk = i & 15;
        Pa[w][i] = __float2bfloat16(pr == pk ? 1.f : 0.f);
        Pb[w][i] = __float2bfloat16((float)i);
    }
    __syncwarp();
    {
        wmma::fragment<wmma::matrix_a, 16, 16, 16, __nv_bfloat16, wmma::row_major> ap;
        wmma::fragment<wmma::matrix_b, 16, 16, 16, __nv_bfloat16, wmma::col_major> bp;
        wmma::fragment<wmma::accumulator, 16, 16, 16, float> cp;
        wmma::load_matrix_sync(ap, &Pa[w][0], 16);
        wmma::load_matrix_sync(bp, &Pb[w][0], 16);
        wmma::fill_fragment(cp, 0.f);
        wmma::mma_sync(cp, ap, bp, cp);
#pragma unroll
        for (int i = 0; i < 8; i++) {
            int v = (int)(cp.x[i] + 0.5f);
            rowi[i] = v & 15;
        }
    }

    const uint4* qsrc = (const uint4*)(g_Q + ((size_t)hb * L_ + q0) * HD_);
    uint4* qdst = (uint4*)Qs;
    for (int i = tid; i < 256; i += 128) qdst[i] = qsrc[i];
    __syncthreads();

    wmma::fragment<wmma::matrix_a, 16, 16, 16, __nv_bfloat16, wmma::row_major> a0, a1;
    wmma::load_matrix_sync(a0, Qs + w * 16 * HD_, HD_);
    wmma::load_matrix_sync(a1, Qs + w * 16 * HD_ + 16, HD_);

    float zpart[8];
#pragma unroll
    for (int i = 0; i < 8; i++) zpart[i] = 0.f;

    for (int kt = 0; kt < 8; kt++) {
        __syncthreads();
        const uint4* ksrc = (const uint4*)(g_K + ((size_t)hb * L_ + kc0 + kt * 64) * HD_);
        uint4* kdst = (uint4*)Ks;
        for (int i = tid; i < 256; i += 128) kdst[i] = ksrc[i];
        __syncthreads();

#pragma unroll
        for (int n = 0; n < 4; n++) {
            wmma::fragment<wmma::matrix_b, 16, 16, 16, __nv_bfloat16, wmma::col_major> b0, b1;
            wmma::load_matrix_sync(b0, Ks + n * 16 * HD_, HD_);
            wmma::load_matrix_sync(b1, Ks + n * 16 * HD_ + 16, HD_);
            wmma::fragment<wmma::accumulator, 16, 16, 16, float> cf;
            wmma::fill_fragment(cf, 0.f);
            wmma::mma_sync(cf, a0, b0, cf);
            wmma::mma_sync(cf, a1, b1, cf);
#pragma unroll
            for (int i = 0; i < 8; i++) zpart[i] += exp2f(cf.x[i]);
        }
    }

    if (lane < 16) zrow[w][lane] = 0.f;
    __syncwarp();
#pragma unroll
    for (int i = 0; i < 8; i++) atomicAdd(&zrow[w][rowi[i]], zpart[i]);
    __syncwarp();
    if (lane < 16) atomicAdd(&g_Z[hb * L_ + q0 + w * 16 + lane], zrow[w][lane]);
}

// Pass 2: diagonal sums. p computed in registers (probed layout), scattered
// to a skewed per-warp bf16 stash (column == diagonal id). Borders pre-zeroed
// so the gather is an unconditional unrolled 16-row sum into the per-block
// Sw window; one global atomic per m per block at the end.
// grid (32, 16, 4), block 128. smem ~29 KB.
__global__ __launch_bounds__(128) void s_kernel() {
    __shared__ __nv_bfloat16 Qs[64 * HD_];
    __shared__ __nv_bfloat16 Ks[64 * HD_];
    __shared__ float invZs[64];
    __shared__ float vvs[512];
    __shared__ __nv_bfloat16 stash[4][16 * 80];
    __shared__ float Sw[4][528];

    int hb = blockIdx.y;
    int q0 = blockIdx.x * 64;
    int kc0 = blockIdx.z * 512;
    if (kc0 + 511 < q0) return;

    int tid = threadIdx.x;
    int w = tid >> 5;
    int lane = tid & 31;
    __nv_bfloat16* stw = &stash[w][0];

    // probe buffers overlay the stash (consumed before stash is used)
    int rowi[8];
    int coli[8];
    {
        __nv_bfloat16* Paw = stw;
        __nv_bfloat16* Pbw = stw + 256;
        for (int i = lane; i < 256; i += 32) {
            int pr = i >> 4;
            int pk = i & 15;
            Paw[i] = __float2bfloat16(pr == pk ? 1.f : 0.f);
            Pbw[i] = __float2bfloat16((float)i);
        }
        __syncwarp();
        wmma::fragment<wmma::matrix_a, 16, 16, 16, __nv_bfloat16, wmma::row_major> ap;
        wmma::fragment<wmma::matrix_b, 16, 16, 16, __nv_bfloat16, wmma::col_major> bp;
        wmma::fragment<wmma::accumulator, 16, 16, 16, float> cp;
        wmma::load_matrix_sync(ap, Paw, 16);
        wmma::load_matrix_sync(bp, Pbw, 16);
        wmma::fill_fragment(cp, 0.f);
        wmma::mma_sync(cp, ap, bp, cp);
#pragma unroll
        for (int i = 0; i < 8; i++) {
            int v = (int)(cp.x[i] + 0.5f);
            rowi[i] = v & 15;
            coli[i] = v >> 4;
        }
        __syncwarp();
    }

    // pre-zero the never-written skew borders (valid region per row r is
    // t in [15-r, 78-r]; column t=79 is never read)
    __nv_bfloat16 bz = __float2bfloat16(0.f);
#pragma unroll
    for (int rr = 0; rr < 16; rr++) {
        if (lane < 15 - rr) stw[rr * 80 + lane] = bz;
        if (lane < rr) stw[rr * 80 + 79 - rr + lane] = bz;
    }

    const uint4* qsrc = (const uint4*)(g_Q + ((size_t)hb * L_ + q0) * HD_);
    uint4* qdst = (uint4*)Qs;
    for (int i = tid; i < 256; i += 128) qdst[i] = qsrc[i];
    if (tid < 64) invZs[tid] = 1.f / g_Z[hb * L_ + q0 + tid];
    for (int i = tid; i < 512; i += 128) vvs[i] = g_vv[hb * L_ + kc0 + i];
    for (int i = tid; i < 4 * 528; i += 128) (&Sw[0][0])[i] = 0.f;
    __syncthreads();

    wmma::fragment<wmma::matrix_a, 16, 16, 16, __nv_bfloat16, wmma::row_major> a0, a1;
    wmma::load_matrix_sync(a0, Qs + w * 16 * HD_, HD_);
    wmma::load_matrix_sync(a1, Qs + w * 16 * HD_ + 16, HD_);

    int q0w = q0 + w * 16;
    float iz[8];
    int soff[8];
#pragma unroll
    for (int i = 0; i < 8; i++) {
        iz[i] = invZs[w * 16 + rowi[i]];
        soff[i] = rowi[i] * 79 + 15;
    }

    for (int kt = 0; kt < 8; kt++) {
        int k0 = kc0 + kt * 64;
        if (k0 + 63 < q0) continue;
        __syncthreads();
        const uint4* ksrc = (const uint4*)(g_K + ((size_t)hb * L_ + k0) * HD_);
        uint4* kdst = (uint4*)Ks;
        for (int i = tid; i < 256; i += 128) kdst[i] = ksrc[i];
        __syncthreads();

#pragma unroll
        for (int n = 0; n < 4; n++) {
            wmma::fragment<wmma::matrix_b, 16, 16, 16, __nv_bfloat16, wmma::col_major> b0, b1;
            wmma::load_matrix_sync(b0, Ks + n * 16 * HD_, HD_);
            wmma::load_matrix_sync(b1, Ks + n * 16 * HD_ + 16, HD_);
            wmma::fragment<wmma::accumulator, 16, 16, 16, float> cf;
            wmma::fill_fragment(cf, 0.f);
            wmma::mma_sync(cf, a0, b0, cf);
            wmma::mma_sync(cf, a1, b1, cf);
#pragma unroll
            for (int i = 0; i < 8; i++) {
                int c = n * 16 + coli[i];
                float p = exp2f(cf.x[i]) * iz[i] * vvs[kt * 64 + c];
                stw[soff[i] + c] = __float2bfloat16(p);
            }
        }
        __syncwarp();

        for (int t = lane; t < 79; t += 32) {
            float sum0 = 0.f;
            float sum1 = 0.f;
#pragma unroll
            for (int rr = 0; rr < 16; rr += 2) {
                sum0 += __bfloat162float(stw[rr * 80 + t]);
                sum1 += __bfloat162float(stw[(rr + 1) * 80 + t]);
            }
            Sw[w][kt * 64 + t] += sum0 + sum1;
        }
        __syncwarp();
    }
    __syncthreads();

    int base = kc0 - q0;
    int mlo = base - 63;
    if (mlo < 0) mlo = 0;
    int mhi = base + 511;
    if (mhi > L_ - 1) mhi = L_ - 1;
    for (int m = mlo + tid; m <= mhi; m += 128) {
        float acc = 0.f;
#pragma unroll
        for (int wp = 0; wp < 4; wp++) {
            int idx = m - base + 16 * wp + 15;
            if (idx >= 0 && idx < 528) acc += Sw[wp][idx];
        }
        atomicAdd(&g_S[hb * L_ + m], acc);
    }
}

__global__ void out_kernel(float* __restrict__ out) {
    int t = blockIdx.x * 256 + threadIdx.x;
    int h = t & 7;
    int m = (t >> 3) & (L_ - 1);
    int b = t >> 14;
    const float* S = g_S + (h * B_ + b) * L_;
    float num = S[m];
    float cnt = 3.f;
    if (m > 0) num += S[m - 1]; else cnt = 2.f;
    if (m < L_ - 1) num += S[m + 1]; else cnt = 2.f;
    out[t] = num / cnt;
}

extern "C" void kernel_launch(void* const* d_in, const int* in_sizes, int n_in,
                              void* d_out, int out_size) {
    const float* x = (const float*)d_in[0];
    const float* pe = (const float*)d_in[1];
    const float* Wq = (const float*)d_in[2];
    const float* bq = (const float*)d_in[3];
    const float* Wk = (const float*)d_in[4];
    const float* bk = (const float*)d_in[5];
    const float* Wv = (const float*)d_in[6];
    float* out = (float*)d_out;

    qk_kernel<<<256, 256>>>(x, pe, Wq, bq, Wk, bk);
    v_kernel<<<128, 256>>>(x, Wv);
    z_kernel<<<dim3(32, 16, 4), 128>>>();
    s_kernel<<<dim3(32, 16, 4), 128>>>();
    out_kernel<<<128, 256>>>(out);
}

// round 15
// speedup vs baseline: 1.6166x; 1.0153x over previous
#include <cuda_runtime.h>
#include <cuda_bf16.h>
#include <mma.h>

using namespace nvcuda;

#define B_ 2
#define L_ 2048
#define D_ 128
#define H_ 8
#define HD_ 32
#define HB_ 16
#define QSCALE 0.2550348f

__device__ float g_Z[HB_ * L_];
__device__ float g_S[HB_ * L_];
__device__ float g_vv[HB_ * L_];
__device__ __nv_bfloat16 g_Q[HB_ * L_ * HD_];
__device__ __nv_bfloat16 g_K[HB_ * L_ * HD_];

__global__ void qk_kernel(const float* __restrict__ x, const float* __restrict__ pe,
                          const float* __restrict__ Wq, const float* __restrict__ bq,
                          const float* __restrict__ Wk, const float* __restrict__ bk) {
    __shared__ float xs[16][D_];
    int row0 = blockIdx.x * 16;
    int tg = blockIdx.x * 256 + threadIdx.x;
    if (tg < HB_ * L_) {
        g_Z[tg] = 0.f;
        g_S[tg] = 0.f;
    }
    for (int i = threadIdx.x; i < 16 * D_; i += 256) {
        int r = i >> 7;
        int d = i & (D_ - 1);
        int row = row0 + r;
        int l = row & (L_ - 1);
        xs[r][d] = x[row * D_ + d] + pe[l * D_ + d];
    }
    __syncthreads();

    int c = threadIdx.x;
    float accq[16];
    float acck[16];
#pragma unroll
    for (int r = 0; r < 16; r++) {
        accq[r] = 0.f;
        acck[r] = 0.f;
    }
#pragma unroll 4
    for (int d = 0; d < D_; d++) {
        float wq = Wq[d * 256 + c];
        float wk = Wk[d * 256 + c];
#pragma unroll
        for (int r = 0; r < 16; r++) {
            float xv = xs[r][d];
            accq[r] = fmaf(xv, wq, accq[r]);
            acck[r] = fmaf(xv, wk, acck[r]);
        }
    }
    float bqv = bq[c];
    float bkv = bk[c];
    int h = c >> 5;
    int hd = c & 31;
#pragma unroll
    for (int r = 0; r < 16; r++) {
        int row = row0 + r;
        int b = row >> 11;
        int l = row & (L_ - 1);
        size_t off = ((size_t)(h * B_ + b) * L_ + l) * HD_ + hd;
        g_Q[off] = __float2bfloat16((accq[r] + bqv) * QSCALE);
        g_K[off] = __float2bfloat16(acck[r] + bkv);
    }
}

__global__ void v_kernel(const float* __restrict__ x, const float* __restrict__ Wv) {
    int t = blockIdx.x * 256 + threadIdx.x;
    int h = t & 7;
    int row = t >> 3;
    const float* xr = x + (size_t)row * D_;
    float acc = 0.f;
#pragma unroll 8
    for (int d = 0; d < D_; d++) acc = fmaf(xr[d], Wv[d * H_ + h], acc);
    float s = 1.f / (1.f + __expf(-acc));
    int b = row >> 11;
    int l = row & (L_ - 1);
    g_vv[(h * B_ + b) * L_ + (L_ - 1 - l)] = s;
}

// Pass 1: Z row sums, exp2 direct from accumulator registers (probed layout).
// Double-buffered K tiles: prefetch next tile during compute, 1 barrier/iter.
// grid (32, 16, 4), block 128.
__global__ __launch_bounds__(128) void z_kernel() {
    __shared__ __nv_bfloat16 Qs[64 * HD_];
    __shared__ __nv_bfloat16 Ks[2][64 * HD_];
    __shared__ __nv_bfloat16 Pa[4][256];
    __shared__ __nv_bfloat16 Pb[4][256];
    __shared__ float zrow[4][16];

    int hb = blockIdx.y;
    int q0 = blockIdx.x * 64;
    int kc0 = blockIdx.z * 512;
    int tid = threadIdx.x;
    int w = tid >> 5;
    int lane = tid & 31;

    int rowi[8];
    for (int i = lane; i < 256; i += 32) {
        int pr = i >> 4;
        int pk = i & 15;
        Pa[w][i] = __float2bfloat16(pr == pk ? 1.f : 0.f);
        Pb[w][i] = __float2bfloat16((float)i);
    }
    __syncwarp();
    {
        wmma::fragment<wmma::matrix_a, 16, 16, 16, __nv_bfloat16, wmma::row_major> ap;
        wmma::fragment<wmma::matrix_b, 16, 16, 16, __nv_bfloat16, wmma::col_major> bp;
        wmma::fragment<wmma::accumulator, 16, 16, 16, float> cp;
        wmma::load_matrix_sync(ap, &Pa[w][0], 16);
        wmma::load_matrix_sync(bp, &Pb[w][0], 16);
        wmma::fill_fragment(cp, 0.f);
        wmma::mma_sync(cp, ap, bp, cp);
#pragma unroll
        for (int i = 0; i < 8; i++) {
            int v = (int)(cp.x[i] + 0.5f);
            rowi[i] = v & 15;
        }
    }

    const uint4* qsrc = (const uint4*)(g_Q + ((size_t)hb * L_ + q0) * HD_);
    uint4* qdst = (uint4*)Qs;
    for (int i = tid; i < 256; i += 128) qdst[i] = qsrc[i];

    const uint4* ksrc = (const uint4*)(g_K + ((size_t)hb * L_ + kc0) * HD_);
    uint4 p0 = ksrc[tid];
    uint4 p1 = ksrc[tid + 128];
    {
        uint4* kd = (uint4*)&Ks[0][0];
        kd[tid] = p0;
        kd[tid + 128] = p1;
    }
    __syncthreads();

    wmma::fragment<wmma::matrix_a, 16, 16, 16, __nv_bfloat16, wmma::row_major> a0, a1;
    wmma::load_matrix_sync(a0, Qs + w * 16 * HD_, HD_);
    wmma::load_matrix_sync(a1, Qs + w * 16 * HD_ + 16, HD_);

    float zpart[8];
#pragma unroll
    for (int i = 0; i < 8; i++) zpart[i] = 0.f;

    for (int kt = 0; kt < 8; kt++) {
        if (kt < 7) {
            p0 = ksrc[(kt + 1) * 256 + tid];
            p1 = ksrc[(kt + 1) * 256 + tid + 128];
        }
        const __nv_bfloat16* Kc = &Ks[kt & 1][0];

#pragma unroll
        for (int n = 0; n < 4; n++) {
            wmma::fragment<wmma::matrix_b, 16, 16, 16, __nv_bfloat16, wmma::col_major> b0, b1;
            wmma::load_matrix_sync(b0, Kc + n * 16 * HD_, HD_);
            wmma::load_matrix_sync(b1, Kc + n * 16 * HD_ + 16, HD_);
            wmma::fragment<wmma::accumulator, 16, 16, 16, float> cf;
            wmma::fill_fragment(cf, 0.f);
            wmma::mma_sync(cf, a0, b0, cf);
            wmma::mma_sync(cf, a1, b1, cf);
#pragma unroll
            for (int i = 0; i < 8; i++) zpart[i] += exp2f(cf.x[i]);
        }

        if (kt < 7) {
            uint4* kd = (uint4*)&Ks[(kt + 1) & 1][0];
            kd[tid] = p0;
            kd[tid + 128] = p1;
            __syncthreads();
        }
    }

    if (lane < 16) zrow[w][lane] = 0.f;
    __syncwarp();
#pragma unroll
    for (int i = 0; i < 8; i++) atomicAdd(&zrow[w][rowi[i]], zpart[i]);
    __syncwarp();
    if (lane < 16) atomicAdd(&g_Z[hb * L_ + q0 + w * 16 + lane], zrow[w][lane]);
}

// Pass 2: diagonal sums. Probed layout, skewed bf16 stash, bf162 pair gather,
// double-buffered K tiles. grid (32, 16, 4), block 128. smem ~33 KB.
__global__ __launch_bounds__(128) void s_kernel() {
    __shared__ __nv_bfloat16 Qs[64 * HD_];
    __shared__ __nv_bfloat16 Ks[2][64 * HD_];
    __shared__ float invZs[64];
    __shared__ float vvs[512];
    __shared__ __nv_bfloat16 stash[4][16 * 80];
    __shared__ float Sw[4][528];

    int hb = blockIdx.y;
    int q0 = blockIdx.x * 64;
    int kc0 = blockIdx.z * 512;
    if (kc0 + 511 < q0) return;

    int tid = threadIdx.x;
    int w = tid >> 5;
    int lane = tid & 31;
    __nv_bfloat16* stw = &stash[w][0];

    // probe buffers overlay the stash (consumed before stash is used)
    int rowi[8];
    int coli[8];
    {
        __nv_bfloat16* Paw = stw;
        __nv_bfloat16* Pbw = stw + 256;
        for (int i = lane; i < 256; i += 32) {
            int pr = i >> 4;
            int pk = i & 15;
            Paw[i] = __float2bfloat16(pr == pk ? 1.f : 0.f);
            Pbw[i] = __float2bfloat16((float)i);
        }
        __syncwarp();
        wmma::fragment<wmma::matrix_a, 16, 16, 16, __nv_bfloat16, wmma::row_major> ap;
        wmma::fragment<wmma::matrix_b, 16, 16, 16, __nv_bfloat16, wmma::col_major> bp;
        wmma::fragment<wmma::accumulator, 16, 16, 16, float> cp;
        wmma::load_matrix_sync(ap, Paw, 16);
        wmma::load_matrix_sync(bp, Pbw, 16);
        wmma::fill_fragment(cp, 0.f);
        wmma::mma_sync(cp, ap, bp, cp);
#pragma unroll
        for (int i = 0; i < 8; i++) {
            int v = (int)(cp.x[i] + 0.5f);
            rowi[i] = v & 15;
            coli[i] = v >> 4;
        }
        __syncwarp();
    }

    // pre-zero never-written skew borders; also column 79 (read by pair loads)
    __nv_bfloat16 bz = __float2bfloat16(0.f);
#pragma unroll
    for (int rr = 0; rr < 16; rr++) {
        if (lane < 15 - rr) stw[rr * 80 + lane] = bz;
        if (lane < rr) stw[rr * 80 + 79 - rr + lane] = bz;
    }
    if (lane < 16) stw[lane * 80 + 79] = bz;

    const uint4* qsrc = (const uint4*)(g_Q + ((size_t)hb * L_ + q0) * HD_);
    uint4* qdst = (uint4*)Qs;
    for (int i = tid; i < 256; i += 128) qdst[i] = qsrc[i];
    if (tid < 64) invZs[tid] = 1.f / g_Z[hb * L_ + q0 + tid];
    for (int i = tid; i < 512; i += 128) vvs[i] = g_vv[hb * L_ + kc0 + i];
    for (int i = tid; i < 4 * 528; i += 128) (&Sw[0][0])[i] = 0.f;

    int kt_start = (q0 > kc0) ? ((q0 - kc0) >> 6) : 0;
    const uint4* ksrc = (const uint4*)(g_K + ((size_t)hb * L_ + kc0) * HD_);
    uint4 p0 = ksrc[kt_start * 256 + tid];
    uint4 p1 = ksrc[kt_start * 256 + tid + 128];
    {
        uint4* kd = (uint4*)&Ks[kt_start & 1][0];
        kd[tid] = p0;
        kd[tid + 128] = p1;
    }
    __syncthreads();

    wmma::fragment<wmma::matrix_a, 16, 16, 16, __nv_bfloat16, wmma::row_major> a0, a1;
    wmma::load_matrix_sync(a0, Qs + w * 16 * HD_, HD_);
    wmma::load_matrix_sync(a1, Qs + w * 16 * HD_ + 16, HD_);

    float iz[8];
    int soff[8];
#pragma unroll
    for (int i = 0; i < 8; i++) {
        iz[i] = invZs[w * 16 + rowi[i]];
        soff[i] = rowi[i] * 79 + 15;
    }

    for (int kt = kt_start; kt < 8; kt++) {
        if (kt < 7) {
            p0 = ksrc[(kt + 1) * 256 + tid];
            p1 = ksrc[(kt + 1) * 256 + tid + 128];
        }
        const __nv_bfloat16* Kc = &Ks[kt & 1][0];

#pragma unroll
        for (int n = 0; n < 4; n++) {
            wmma::fragment<wmma::matrix_b, 16, 16, 16, __nv_bfloat16, wmma::col_major> b0, b1;
            wmma::load_matrix_sync(b0, Kc + n * 16 * HD_, HD_);
            wmma::load_matrix_sync(b1, Kc + n * 16 * HD_ + 16, HD_);
            wmma::fragment<wmma::accumulator, 16, 16, 16, float> cf;
            wmma::fill_fragment(cf, 0.f);
            wmma::mma_sync(cf, a0, b0, cf);
            wmma::mma_sync(cf, a1, b1, cf);
#pragma unroll
            for (int i = 0; i < 8; i++) {
                int c = n * 16 + coli[i];
                float p = exp2f(cf.x[i]) * iz[i] * vvs[kt * 64 + c];
                stw[soff[i] + c] = __float2bfloat16(p);
            }
        }
        __syncwarp();

        // pair gather: column pairs (2pc, 2pc+1); pair (78,79) adds 0 for t=79
        for (int pc = lane; pc < 40; pc += 32) {
            float se = 0.f;
            float so = 0.f;
#pragma unroll
            for (int rr = 0; rr < 16; rr++) {
                __nv_bfloat162 v2 = *(const __nv_bfloat162*)(stw + rr * 80 + 2 * pc);
                se += __bfloat162float(v2.x);
                so += __bfloat162float(v2.y);
            }
            int idx = kt * 64 + 2 * pc;
            Sw[w][idx] += se;
            Sw[w][idx + 1] += so;
        }
        __syncwarp();

        if (kt < 7) {
            uint4* kd = (uint4*)&Ks[(kt + 1) & 1][0];
            kd[tid] = p0;
            kd[tid + 128] = p1;
            __syncthreads();
        }
    }
    __syncthreads();

    int base = kc0 - q0;
    int mlo = base - 63;
    if (mlo < 0) mlo = 0;
    int mhi = base + 511;
    if (mhi > L_ - 1) mhi = L_ - 1;
    for (int m = mlo + tid; m <= mhi; m += 128) {
        float acc = 0.f;
#pragma unroll
        for (int wp = 0; wp < 4; wp++) {
            int idx = m - base + 16 * wp + 15;
            if (idx >= 0 && idx < 528) acc += Sw[wp][idx];
        }
        atomicAdd(&g_S[hb * L_ + m], acc);
    }
}

__global__ void out_kernel(float* __restrict__ out) {
    int t = blockIdx.x * 256 + threadIdx.x;
    int h = t & 7;
    int m = (t >> 3) & (L_ - 1);
    int b = t >> 14;
    const float* S = g_S + (h * B_ + b) * L_;
    float num = S[m];
    float cnt = 3.f;
    if (m > 0) num += S[m - 1]; else cnt = 2.f;
    if (m < L_ - 1) num += S[m + 1]; else cnt = 2.f;
    out[t] = num / cnt;
}

extern "C" void kernel_launch(void* const* d_in, const int* in_sizes, int n_in,
                              void* d_out, int out_size) {
    const float* x = (const float*)d_in[0];
    const float* pe = (const float*)d_in[1];
    const float* Wq = (const float*)d_in[2];
    const float* bq = (const float*)d_in[3];
    const float* Wk = (const float*)d_in[4];
    const float* bk = (const float*)d_in[5];
    const float* Wv = (const float*)d_in[6];
    float* out = (float*)d_out;

    qk_kernel<<<256, 256>>>(x, pe, Wq, bq, Wk, bk);
    v_kernel<<<128, 256>>>(x, Wv);
    z_kernel<<<dim3(32, 16, 4), 128>>>();
    s_kernel<<<dim3(32, 16, 4), 128>>>();
    out_kernel<<<128, 256>>>(out);
}

// round 16
// speedup vs baseline: 1.7058x; 1.0552x over previous
#include <cuda_runtime.h>
#include <cuda_bf16.h>
#include <mma.h>

using namespace nvcuda;

#define B_ 2
#define L_ 2048
#define D_ 128
#define H_ 8
#define HD_ 32
#define HB_ 16
#define QSCALE 0.2550348f
#define STRIDE 82

__device__ float g_Z[HB_ * L_];
__device__ float g_S[HB_ * L_];
__device__ float g_vv[HB_ * L_];
__device__ __nv_bfloat16 g_Q[HB_ * L_ * HD_];
__device__ __nv_bfloat16 g_K[HB_ * L_ * HD_];

__global__ void qk_kernel(const float* __restrict__ x, const float* __restrict__ pe,
                          const float* __restrict__ Wq, const float* __restrict__ bq,
                          const float* __restrict__ Wk, const float* __restrict__ bk) {
    __shared__ float xs[16][D_];
    int row0 = blockIdx.x * 16;
    int tg = blockIdx.x * 256 + threadIdx.x;
    if (tg < HB_ * L_) {
        g_Z[tg] = 0.f;
        g_S[tg] = 0.f;
    }
    for (int i = threadIdx.x; i < 16 * D_; i += 256) {
        int r = i >> 7;
        int d = i & (D_ - 1);
        int row = row0 + r;
        int l = row & (L_ - 1);
        xs[r][d] = x[row * D_ + d] + pe[l * D_ + d];
    }
    __syncthreads();

    int c = threadIdx.x;
    float accq[16];
    float acck[16];
#pragma unroll
    for (int r = 0; r < 16; r++) {
        accq[r] = 0.f;
        acck[r] = 0.f;
    }
#pragma unroll 4
    for (int d = 0; d < D_; d++) {
        float wq = Wq[d * 256 + c];
        float wk = Wk[d * 256 + c];
#pragma unroll
        for (int r = 0; r < 16; r++) {
            float xv = xs[r][d];
            accq[r] = fmaf(xv, wq, accq[r]);
            acck[r] = fmaf(xv, wk, acck[r]);
        }
    }
    float bqv = bq[c];
    float bkv = bk[c];
    int h = c >> 5;
    int hd = c & 31;
#pragma unroll
    for (int r = 0; r < 16; r++) {
        int row = row0 + r;
        int b = row >> 11;
        int l = row & (L_ - 1);
        size_t off = ((size_t)(h * B_ + b) * L_ + l) * HD_ + hd;
        g_Q[off] = __float2bfloat16((accq[r] + bqv) * QSCALE);
        g_K[off] = __float2bfloat16(acck[r] + bkv);
    }
}

__global__ void v_kernel(const float* __restrict__ x, const float* __restrict__ Wv) {
    int t = blockIdx.x * 256 + threadIdx.x;
    int h = t & 7;
    int row = t >> 3;
    const float* xr = x + (size_t)row * D_;
    float acc = 0.f;
#pragma unroll 8
    for (int d = 0; d < D_; d++) acc = fmaf(xr[d], Wv[d * H_ + h], acc);
    float s = 1.f / (1.f + __expf(-acc));
    int b = row >> 11;
    int l = row & (L_ - 1);
    g_vv[(h * B_ + b) * L_ + (L_ - 1 - l)] = s;
}

// Pass 1: Z row sums, exp2 direct from accumulator registers (probed layout).
// Probe buffers overlay Ks[0] (consumed before K loads). Double-buffered K.
// grid (32, 16, 4), block 128. smem ~12.3 KB.
__global__ __launch_bounds__(128) void z_kernel() {
    __shared__ __nv_bfloat16 Qs[64 * HD_];
    __shared__ __nv_bfloat16 Ks[2][64 * HD_];
    __shared__ float zrow[4][16];

    int hb = blockIdx.y;
    int q0 = blockIdx.x * 64;
    int kc0 = blockIdx.z * 512;
    int tid = threadIdx.x;
    int w = tid >> 5;
    int lane = tid & 31;

    int rowi[8];
    {
        __nv_bfloat16* Paw = &Ks[0][0] + w * 512;
        __nv_bfloat16* Pbw = Paw + 256;
        for (int i = lane; i < 256; i += 32) {
            int pr = i >> 4;
            int pk = i & 15;
            Paw[i] = __float2bfloat16(pr == pk ? 1.f : 0.f);
            Pbw[i] = __float2bfloat16((float)i);
        }
        __syncwarp();
        wmma::fragment<wmma::matrix_a, 16, 16, 16, __nv_bfloat16, wmma::row_major> ap;
        wmma::fragment<wmma::matrix_b, 16, 16, 16, __nv_bfloat16, wmma::col_major> bp;
        wmma::fragment<wmma::accumulator, 16, 16, 16, float> cp;
        wmma::load_matrix_sync(ap, Paw, 16);
        wmma::load_matrix_sync(bp, Pbw, 16);
        wmma::fill_fragment(cp, 0.f);
        wmma::mma_sync(cp, ap, bp, cp);
#pragma unroll
        for (int i = 0; i < 8; i++) {
            int v = (int)(cp.x[i] + 0.5f);
            rowi[i] = v & 15;
        }
    }
    __syncthreads();

    const uint4* qsrc = (const uint4*)(g_Q + ((size_t)hb * L_ + q0) * HD_);
    uint4* qdst = (uint4*)Qs;
    for (int i = tid; i < 256; i += 128) qdst[i] = qsrc[i];

    const uint4* ksrc = (const uint4*)(g_K + ((size_t)hb * L_ + kc0) * HD_);
    uint4 p0 = ksrc[tid];
    uint4 p1 = ksrc[tid + 128];
    {
        uint4* kd = (uint4*)&Ks[0][0];
        kd[tid] = p0;
        kd[tid + 128] = p1;
    }
    __syncthreads();

    wmma::fragment<wmma::matrix_a, 16, 16, 16, __nv_bfloat16, wmma::row_major> a0, a1;
    wmma::load_matrix_sync(a0, Qs + w * 16 * HD_, HD_);
    wmma::load_matrix_sync(a1, Qs + w * 16 * HD_ + 16, HD_);

    float zpart[8];
#pragma unroll
    for (int i = 0; i < 8; i++) zpart[i] = 0.f;

    for (int kt = 0; kt < 8; kt++) {
        if (kt < 7) {
            p0 = ksrc[(kt + 1) * 256 + tid];
            p1 = ksrc[(kt + 1) * 256 + tid + 128];
        }
        const __nv_bfloat16* Kc = &Ks[kt & 1][0];

#pragma unroll
        for (int n = 0; n < 4; n++) {
            wmma::fragment<wmma::matrix_b, 16, 16, 16, __nv_bfloat16, wmma::col_major> b0, b1;
            wmma::load_matrix_sync(b0, Kc + n * 16 * HD_, HD_);
            wmma::load_matrix_sync(b1, Kc + n * 16 * HD_ + 16, HD_);
            wmma::fragment<wmma::accumulator, 16, 16, 16, float> cf;
            wmma::fill_fragment(cf, 0.f);
            wmma::mma_sync(cf, a0, b0, cf);
            wmma::mma_sync(cf, a1, b1, cf);
#pragma unroll
            for (int i = 0; i < 8; i++) zpart[i] += exp2f(cf.x[i]);
        }

        if (kt < 7) {
            uint4* kd = (uint4*)&Ks[(kt + 1) & 1][0];
            kd[tid] = p0;
            kd[tid + 128] = p1;
            __syncthreads();
        }
    }

    if (lane < 16) zrow[w][lane] = 0.f;
    __syncwarp();
#pragma unroll
    for (int i = 0; i < 8; i++) atomicAdd(&zrow[w][rowi[i]], zpart[i]);
    __syncwarp();
    if (lane < 16) atomicAdd(&g_Z[hb * L_ + q0 + w * 16 + lane], zrow[w][lane]);
}

// Pass 2: diagonal sums. Row-pair skew (j = c - (r&~1) + 16) makes element
// pairs 4-byte aligned -> packed bf162 scatter (16 STS vs 32). Stride 82 is
// conflict-free. Gather: diag t reads col t+1 on even rows, t+2 on odd rows.
// Single K buffer + register prefetch. grid (32, 16, 4), block 128. ~29.4 KB.
__global__ __launch_bounds__(128) void s_kernel() {
    __shared__ __nv_bfloat16 Qs[64 * HD_];
    __shared__ __nv_bfloat16 Ks[64 * HD_];
    __shared__ float invZs[64];
    __shared__ float vvs[512];
    __shared__ __nv_bfloat16 stash[4][16 * STRIDE];
    __shared__ float Sw[4][528];

    int hb = blockIdx.y;
    int q0 = blockIdx.x * 64;
    int kc0 = blockIdx.z * 512;
    if (kc0 + 511 < q0) return;

    int tid = threadIdx.x;
    int w = tid >> 5;
    int lane = tid & 31;
    __nv_bfloat16* stw = &stash[w][0];

    int rowi[8];
    int coli[8];
    {
        __nv_bfloat16* Paw = stw;
        __nv_bfloat16* Pbw = stw + 256;
        for (int i = lane; i < 256; i += 32) {
            int pr = i >> 4;
            int pk = i & 15;
            Paw[i] = __float2bfloat16(pr == pk ? 1.f : 0.f);
            Pbw[i] = __float2bfloat16((float)i);
        }
        __syncwarp();
        wmma::fragment<wmma::matrix_a, 16, 16, 16, __nv_bfloat16, wmma::row_major> ap;
        wmma::fragment<wmma::matrix_b, 16, 16, 16, __nv_bfloat16, wmma::col_major> bp;
        wmma::fragment<wmma::accumulator, 16, 16, 16, float> cp;
        wmma::load_matrix_sync(ap, Paw, 16);
        wmma::load_matrix_sync(bp, Pbw, 16);
        wmma::fill_fragment(cp, 0.f);
        wmma::mma_sync(cp, ap, bp, cp);
#pragma unroll
        for (int i = 0; i < 8; i++) {
            int v = (int)(cp.x[i] + 0.5f);
            rowi[i] = v & 15;
            coli[i] = v >> 4;
        }
        __syncwarp();
    }

    // verify pair structure (warp-uniform); scalar fallback if violated
    bool pok = true;
#pragma unroll
    for (int i = 0; i < 8; i += 2) {
        pok = pok && (rowi[i + 1] == rowi[i]) && (coli[i + 1] == coli[i] + 1) && ((coli[i] & 1) == 0);
    }
    pok = __all_sync(0xffffffffu, pok);

    // zero skew borders: row r valid j in [16-(r&~1), 79-(r&~1)]; reads reach j=80
    __nv_bfloat16 bz = __float2bfloat16(0.f);
#pragma unroll
    for (int rr = 0; rr < 16; rr++) {
        int re = rr & ~1;
        if (lane < 16 - re) stw[rr * STRIDE + lane] = bz;
        if (lane < 1 + re) stw[rr * STRIDE + 80 - re + lane] = bz;
    }

    const uint4* qsrc = (const uint4*)(g_Q + ((size_t)hb * L_ + q0) * HD_);
    uint4* qdst = (uint4*)Qs;
    for (int i = tid; i < 256; i += 128) qdst[i] = qsrc[i];
    if (tid < 64) invZs[tid] = 1.f / g_Z[hb * L_ + q0 + tid];
    for (int i = tid; i < 512; i += 128) vvs[i] = g_vv[hb * L_ + kc0 + i];
    for (int i = tid; i < 4 * 528; i += 128) (&Sw[0][0])[i] = 0.f;

    int kt_start = (q0 > kc0) ? ((q0 - kc0) >> 6) : 0;
    const uint4* ksrc = (const uint4*)(g_K + ((size_t)hb * L_ + kc0) * HD_);
    uint4 p0 = ksrc[kt_start * 256 + tid];
    uint4 p1 = ksrc[kt_start * 256 + tid + 128];
    {
        uint4* kd = (uint4*)Ks;
        kd[tid] = p0;
        kd[tid + 128] = p1;
    }
    __syncthreads();

    wmma::fragment<wmma::matrix_a, 16, 16, 16, __nv_bfloat16, wmma::row_major> a0, a1;
    wmma::load_matrix_sync(a0, Qs + w * 16 * HD_, HD_);
    wmma::load_matrix_sync(a1, Qs + w * 16 * HD_ + 16, HD_);

    float iz[8];
    int soff2[8];
#pragma unroll
    for (int i = 0; i < 8; i++) {
        iz[i] = invZs[w * 16 + rowi[i]];
        soff2[i] = rowi[i] * STRIDE + 16 - (rowi[i] & ~1);
    }

    for (int kt = kt_start; kt < 8; kt++) {
        if (kt < 7) {
            p0 = ksrc[(kt + 1) * 256 + tid];
            p1 = ksrc[(kt + 1) * 256 + tid + 128];
        }

#pragma unroll
        for (int n = 0; n < 4; n++) {
            wmma::fragment<wmma::matrix_b, 16, 16, 16, __nv_bfloat16, wmma::col_major> b0, b1;
            wmma::load_matrix_sync(b0, Ks + n * 16 * HD_, HD_);
            wmma::load_matrix_sync(b1, Ks + n * 16 * HD_ + 16, HD_);
            wmma::fragment<wmma::accumulator, 16, 16, 16, float> cf;
            wmma::fill_fragment(cf, 0.f);
            wmma::mma_sync(cf, a0, b0, cf);
            wmma::mma_sync(cf, a1, b1, cf);

            if (pok) {
#pragma unroll
                for (int i = 0; i < 8; i += 2) {
                    int c = n * 16 + coli[i];
                    float2 vv2 = *(const float2*)(vvs + kt * 64 + c);
                    float pa = exp2f(cf.x[i]) * iz[i] * vv2.x;
                    float pb = exp2f(cf.x[i + 1]) * iz[i] * vv2.y;
                    __nv_bfloat162 hv;
                    hv.x = __float2bfloat16(pa);
                    hv.y = __float2bfloat16(pb);
                    *(__nv_bfloat162*)(stw + soff2[i] + c) = hv;
                }
            } else {
#pragma unroll
                for (int i = 0; i < 8; i++) {
                    int c = n * 16 + coli[i];
                    float p = exp2f(cf.x[i]) * iz[i] * vvs[kt * 64 + c];
                    stw[soff2[i] + c] = __float2bfloat16(p);
                }
            }
        }
        __syncwarp();

        for (int t = lane; t < 79; t += 32) {
            float se = 0.f;
            float so = 0.f;
#pragma unroll
            for (int rr = 0; rr < 16; rr += 2) {
                se += __bfloat162float(stw[rr * STRIDE + t + 1]);
                so += __bfloat162float(stw[(rr + 1) * STRIDE + t + 2]);
            }
            Sw[w][kt * 64 + t] += se + so;
        }
        __syncwarp();

        if (kt < 7) {
            __syncthreads();
            uint4* kd = (uint4*)Ks;
            kd[tid] = p0;
            kd[tid + 128] = p1;
            __syncthreads();
        }
    }
    __syncthreads();

    int base = kc0 - q0;
    int mlo = base - 63;
    if (mlo < 0) mlo = 0;
    int mhi = base + 511;
    if (mhi > L_ - 1) mhi = L_ - 1;
    for (int m = mlo + tid; m <= mhi; m += 128) {
        float acc = 0.f;
#pragma unroll
        for (int wp = 0; wp < 4; wp++) {
            int idx = m - base + 16 * wp + 15;
            if (idx >= 0 && idx < 528) acc += Sw[wp][idx];
        }
        atomicAdd(&g_S[hb * L_ + m], acc);
    }
}

__global__ void out_kernel(float* __restrict__ out) {
    int t = blockIdx.x * 256 + threadIdx.x;
    int h = t & 7;
    int m = (t >> 3) & (L_ - 1);
    int b = t >> 14;
    const float* S = g_S + (h * B_ + b) * L_;
    float num = S[m];
    float cnt = 3.f;
    if (m > 0) num += S[m - 1]; else cnt = 2.f;
    if (m < L_ - 1) num += S[m + 1]; else cnt = 2.f;
    out[t] = num / cnt;
}

extern "C" void kernel_launch(void* const* d_in, const int* in_sizes, int n_in,
                              void* d_out, int out_size) {
    const float* x = (const float*)d_in[0];
    const float* pe = (const float*)d_in[1];
    const float* Wq = (const float*)d_in[2];
    const float* bq = (const float*)d_in[3];
    const float* Wk = (const float*)d_in[4];
    const float* bk = (const float*)d_in[5];
    const float* Wv = (const float*)d_in[6];
    float* out = (float*)d_out;

    qk_kernel<<<256, 256>>>(x, pe, Wq, bq, Wk, bk);
    v_kernel<<<128, 256>>>(x, Wv);
    z_kernel<<<dim3(32, 16, 4), 128>>>();
    s_kernel<<<dim3(32, 16, 4), 128>>>();
    out_kernel<<<128, 256>>>(out);
}